// round 3
// baseline (speedup 1.0000x reference)
#include <cuda_runtime.h>
#include <cuda_bf16.h>
#include <math.h>

#define N_NODES   20000
#define N_EDGES   320000
#define E_TOT     (N_EDGES + N_NODES)   // 340000 with self loops
#define NUM_GRAPHS 64
#define MAXC      256

// ---------------- scratch (alloc-free: __device__ globals) ----------------
__device__ __align__(16) float g_h   [N_NODES * MAXC];
__device__ __align__(16) float g_xl  [N_NODES * MAXC];
__device__ __align__(16) float g_xr  [N_NODES * MAXC];
__device__ __align__(16) float g_ex  [E_TOT * 4];
__device__ __align__(16) float g_max [N_NODES * 4];
__device__ __align__(16) float g_den [N_NODES * 4];
__device__ __align__(16) float g_pool[NUM_GRAPHS * 64];
__device__ int g_src[E_TOT];
__device__ int g_dst[E_TOT];
__device__ int g_batch[N_NODES];
__device__ int g_is64;

// ---------------- helpers ----------------
__device__ __forceinline__ float lrelu(float v) { return v > 0.f ? v : 0.2f * v; }

__device__ __forceinline__ void atomicMaxF(float* addr, float value) {
    if (value >= 0.f) atomicMax((int*)addr, __float_as_int(value));
    else              atomicMin((unsigned int*)addr, __float_as_uint(value));
}

// -------- dtype detection: int64 indices have all-zero high words ----------
__global__ void detect_dtype(const int* __restrict__ ei32)
{
    int nonzero = 0;
    #pragma unroll 8
    for (int i = 0; i < 2048; i += 2) nonzero += (ei32[i + 1] != 0);
    g_is64 = (nonzero == 0) ? 1 : 0;
}

// -------- normalize edge_index + batch into int32, append self loops -------
__global__ void convert_indices(const void* __restrict__ ei_raw,
                                const void* __restrict__ batch_raw)
{
    int is64 = g_is64;
    int idx = blockIdx.x * blockDim.x + threadIdx.x;
    if (idx < N_EDGES) {
        if (is64) {
            const long long* e = (const long long*)ei_raw;
            g_src[idx] = (int)e[idx];
            g_dst[idx] = (int)e[N_EDGES + idx];
        } else {
            const int* e = (const int*)ei_raw;
            g_src[idx] = e[idx];
            g_dst[idx] = e[N_EDGES + idx];
        }
    } else if (idx < E_TOT) {
        g_src[idx] = idx - N_EDGES;
        g_dst[idx] = idx - N_EDGES;
    }
    if (idx < N_NODES) {
        g_batch[idx] = is64 ? (int)((const long long*)batch_raw)[idx]
                            : ((const int*)batch_raw)[idx];
    }
}

// ---------------- GEMM: C = A[N,K] @ W[K,M]; z picks (Wl->Xl)/(Wr->Xr) -----
__global__ void gemm_dual(const float* __restrict__ A,
                          const float* __restrict__ Wl, const float* __restrict__ Wr,
                          float* __restrict__ Xl, float* __restrict__ Xr,
                          int N, int K, int M)
{
    const float* B = blockIdx.z ? Wr : Wl;
    float*       C = blockIdx.z ? Xr : Xl;

    __shared__ float As[16][65];
    __shared__ float Bs[16][65];

    int tid = threadIdx.x;           // 256 threads
    int tx = tid & 15, ty = tid >> 4;
    int row0 = blockIdx.x * 64;
    int col0 = blockIdx.y * 64;

    float acc[4][4] = {};

    for (int k0 = 0; k0 < K; k0 += 16) {
        #pragma unroll
        for (int i = tid; i < 64 * 16; i += 256) {
            int r = i >> 4, kk = i & 15;
            int gr = row0 + r;
            As[kk][r] = (gr < N) ? A[(size_t)gr * K + k0 + kk] : 0.f;
        }
        #pragma unroll
        for (int i = tid; i < 16 * 64; i += 256) {
            int kk = i >> 6, c = i & 63;
            Bs[kk][c] = B[(size_t)(k0 + kk) * M + col0 + c];
        }
        __syncthreads();
        #pragma unroll
        for (int kk = 0; kk < 16; kk++) {
            float a[4], b[4];
            #pragma unroll
            for (int i = 0; i < 4; i++) a[i] = As[kk][ty * 4 + i];
            #pragma unroll
            for (int j = 0; j < 4; j++) b[j] = Bs[kk][tx * 4 + j];
            #pragma unroll
            for (int i = 0; i < 4; i++)
                #pragma unroll
                for (int j = 0; j < 4; j++)
                    acc[i][j] = fmaf(a[i], b[j], acc[i][j]);
        }
        __syncthreads();
    }
    #pragma unroll
    for (int i = 0; i < 4; i++) {
        int r = row0 + ty * 4 + i;
        if (r < N) {
            #pragma unroll
            for (int j = 0; j < 4; j++)
                C[(size_t)r * M + col0 + tx * 4 + j] = acc[i][j];
        }
    }
}

// -------- init per layer: agg = bias (broadcast), max = -inf, den = 0 ------
__global__ void init_layer(float* __restrict__ agg, float* __restrict__ nmax,
                           float* __restrict__ den, const float* __restrict__ bias,
                           int HC, int H)
{
    int idx = blockIdx.x * blockDim.x + threadIdx.x;
    int tot = N_NODES * HC;
    if (idx < tot) agg[idx] = bias[idx % HC];
    if (idx < N_NODES * H) { nmax[idx] = -INFINITY; den[idx] = 0.f; }
}

// -------- pass 1: per-edge per-head logits + segment max (warp/edge) -------
template<int H>
__global__ void edge_logits(const float* __restrict__ xl, const float* __restrict__ xr,
                            const float* __restrict__ att,
                            float* __restrict__ logits, float* __restrict__ nmax)
{
    int w = (blockIdx.x * blockDim.x + threadIdx.x) >> 5;
    int lane = threadIdx.x & 31;
    if (w >= E_TOT) return;
    int src = g_src[w], dst = g_dst[w];

    if (H == 4) {
        const float4* pl = (const float4*)(xl + (size_t)src * 256) + lane * 2;
        const float4* pr = (const float4*)(xr + (size_t)dst * 256) + lane * 2;
        const float4* pa = (const float4*)att + lane * 2;
        float s = 0.f;
        #pragma unroll
        for (int q = 0; q < 2; q++) {
            float4 a = pl[q], b = pr[q], t = pa[q];
            s += lrelu(a.x + b.x) * t.x + lrelu(a.y + b.y) * t.y
               + lrelu(a.z + b.z) * t.z + lrelu(a.w + b.w) * t.w;
        }
        s += __shfl_xor_sync(0xffffffffu, s, 1);
        s += __shfl_xor_sync(0xffffffffu, s, 2);
        s += __shfl_xor_sync(0xffffffffu, s, 4);
        if ((lane & 7) == 0) {
            int h = lane >> 3;
            logits[(size_t)w * 4 + h] = s;
            atomicMaxF(&nmax[dst * 4 + h], s);
        }
    } else {
        const float2* pl = (const float2*)(xl + (size_t)src * 64) + lane;
        const float2* pr = (const float2*)(xr + (size_t)dst * 64) + lane;
        const float2* pa = (const float2*)att + lane;
        float2 a = *pl, b = *pr, t = *pa;
        float s = lrelu(a.x + b.x) * t.x + lrelu(a.y + b.y) * t.y;
        #pragma unroll
        for (int o = 1; o < 32; o <<= 1) s += __shfl_xor_sync(0xffffffffu, s, o);
        if (lane == 0) {
            logits[w] = s;
            atomicMaxF(&nmax[dst], s);
        }
    }
}

// -------- pass 2: exp(logit - max), accumulate denominator -----------------
template<int H>
__global__ void edge_exp(float* __restrict__ logits,
                         const float* __restrict__ nmax, float* __restrict__ den)
{
    int idx = blockIdx.x * blockDim.x + threadIdx.x;
    if (idx >= E_TOT * H) return;
    int e = (H == 4) ? (idx >> 2) : idx;
    int h = (H == 4) ? (idx & 3) : 0;
    int dst = g_dst[e];
    float ex = expf(logits[idx] - nmax[dst * H + h]);
    logits[idx] = ex;
    atomicAdd(&den[dst * H + h], ex);
}

// -------- pass 3: agg[dst] += alpha * xl[src] (warp/edge, vector RED) ------
template<int H>
__global__ void edge_aggregate(const float* __restrict__ xl,
                               const float* __restrict__ ex, const float* __restrict__ den,
                               float* __restrict__ agg)
{
    int w = (blockIdx.x * blockDim.x + threadIdx.x) >> 5;
    int lane = threadIdx.x & 31;
    if (w >= E_TOT) return;
    int src = g_src[w], dst = g_dst[w];

    if (H == 4) {
        int h = lane >> 3;
        float alpha = ex[(size_t)w * 4 + h] / den[dst * 4 + h];
        const float4* pl = (const float4*)(xl + (size_t)src * 256) + lane * 2;
        float4*       pd = (float4*)(agg + (size_t)dst * 256) + lane * 2;
        #pragma unroll
        for (int q = 0; q < 2; q++) {
            float4 v = pl[q];
            atomicAdd(&pd[q], make_float4(alpha * v.x, alpha * v.y, alpha * v.z, alpha * v.w));
        }
    } else {
        float alpha = ex[w] / den[dst];
        const float2* pl = (const float2*)(xl + (size_t)src * 64) + lane;
        float2*       pd = (float2*)(agg + (size_t)dst * 64) + lane;
        float2 v = *pl;
        atomicAdd(pd, make_float2(alpha * v.x, alpha * v.y));
    }
}

// -------- pooling: batch is sorted -> run-length local accumulation --------
__global__ void pool_init(float* __restrict__ pooled)
{
    int idx = blockIdx.x * blockDim.x + threadIdx.x;
    if (idx < NUM_GRAPHS * 64) pooled[idx] = 0.f;
}

__global__ void pool_kernel(const float* __restrict__ h,
                            float* __restrict__ pooled)
{
    const int CHUNK = 256;
    int c = threadIdx.x;                  // 64 threads = channels
    int n0 = blockIdx.x * CHUNK;
    int n1 = min(n0 + CHUNK, N_NODES);
    if (n0 >= N_NODES) return;
    float acc = 0.f;
    int cur = g_batch[n0];
    for (int n = n0; n < n1; n++) {
        int g = g_batch[n];
        if (g != cur) {
            atomicAdd(&pooled[cur * 64 + c], acc);
            acc = 0.f; cur = g;
        }
        acc += h[(size_t)n * 64 + c];
    }
    atomicAdd(&pooled[cur * 64 + c], acc);
}

// -------- head: BN (eval) + FC ---------------------------------------------
__global__ void head_kernel(const float* __restrict__ pooled,
                            const float* __restrict__ gamma, const float* __restrict__ beta,
                            const float* __restrict__ mean,  const float* __restrict__ var,
                            const float* __restrict__ fcw,   const float* __restrict__ fcb,
                            float* __restrict__ out)
{
    int idx = blockIdx.x * blockDim.x + threadIdx.x;
    if (idx >= NUM_GRAPHS * 32) return;
    int g = idx >> 5, l = idx & 31;
    float s = 0.f;
    #pragma unroll 8
    for (int c = 0; c < 64; c++) {
        float xn = (pooled[g * 64 + c] - mean[c]) * rsqrtf(var[c] + 1e-5f) * gamma[c] + beta[c];
        s = fmaf(xn, fcw[c * 32 + l], s);
    }
    out[idx] = s + fcb[l];
}

// ---------------------------------------------------------------------------
static void run_layer(const float* hin, int K, int H,
                      const float* Wl, const float* Wr,
                      const float* att, const float* bias,
                      float* xl, float* xr, float* agg,
                      float* ex, float* nmax, float* den)
{
    int M = H * 64;
    dim3 ggrid((N_NODES + 63) / 64, M / 64, 2);
    gemm_dual<<<ggrid, 256>>>(hin, Wl, Wr, xl, xr, N_NODES, K, M);

    int tot = N_NODES * M;
    init_layer<<<(tot + 255) / 256, 256>>>(agg, nmax, den, bias, M, H);

    int warp_blocks = (E_TOT * 32 + 255) / 256;
    if (H == 4) {
        edge_logits<4><<<warp_blocks, 256>>>(xl, xr, att, ex, nmax);
        edge_exp<4><<<(E_TOT * 4 + 255) / 256, 256>>>(ex, nmax, den);
        edge_aggregate<4><<<warp_blocks, 256>>>(xl, ex, den, agg);
    } else {
        edge_logits<1><<<warp_blocks, 256>>>(xl, xr, att, ex, nmax);
        edge_exp<1><<<(E_TOT + 255) / 256, 256>>>(ex, nmax, den);
        edge_aggregate<1><<<warp_blocks, 256>>>(xl, ex, den, agg);
    }
}

extern "C" void kernel_launch(void* const* d_in, const int* in_sizes, int n_in,
                              void* d_out, int out_size)
{
    const float* x     = (const float*)d_in[0];
    const void*  ei    = d_in[1];
    const void*  batch = d_in[2];
    const float* Wl0 = (const float*)d_in[3];
    const float* Wr0 = (const float*)d_in[4];
    const float* att0= (const float*)d_in[5];
    const float* b0  = (const float*)d_in[6];
    const float* Wl1 = (const float*)d_in[7];
    const float* Wr1 = (const float*)d_in[8];
    const float* att1= (const float*)d_in[9];
    const float* b1  = (const float*)d_in[10];
    const float* Wl2 = (const float*)d_in[11];
    const float* Wr2 = (const float*)d_in[12];
    const float* att2= (const float*)d_in[13];
    const float* b2  = (const float*)d_in[14];
    const float* bng = (const float*)d_in[15];
    const float* bnb = (const float*)d_in[16];
    const float* bnm = (const float*)d_in[17];
    const float* bnv = (const float*)d_in[18];
    const float* fcw = (const float*)d_in[19];
    const float* fcb = (const float*)d_in[20];
    float* out = (float*)d_out;

    float *p_h, *p_xl, *p_xr, *p_ex, *p_max, *p_den, *p_pool;
    cudaGetSymbolAddress((void**)&p_h,    g_h);
    cudaGetSymbolAddress((void**)&p_xl,   g_xl);
    cudaGetSymbolAddress((void**)&p_xr,   g_xr);
    cudaGetSymbolAddress((void**)&p_ex,   g_ex);
    cudaGetSymbolAddress((void**)&p_max,  g_max);
    cudaGetSymbolAddress((void**)&p_den,  g_den);
    cudaGetSymbolAddress((void**)&p_pool, g_pool);

    // normalize index dtypes (int32 vs int64) into int32 scratch
    detect_dtype<<<1, 1>>>((const int*)ei);
    convert_indices<<<(E_TOT + 255) / 256, 256>>>(ei, batch);

    // layer 0: in=128, H=4  (x -> g_h[.,256])
    run_layer(x,   128, 4, Wl0, Wr0, att0, b0, p_xl, p_xr, p_h, p_ex, p_max, p_den);
    // layer 1: in=256, H=4  (g_h -> g_h)
    run_layer(p_h, 256, 4, Wl1, Wr1, att1, b1, p_xl, p_xr, p_h, p_ex, p_max, p_den);
    // layer 2: in=256, H=1  (g_h -> g_h[.,64])
    run_layer(p_h, 256, 1, Wl2, Wr2, att2, b2, p_xl, p_xr, p_h, p_ex, p_max, p_den);

    // global add pool + BN + FC
    pool_init<<<(NUM_GRAPHS * 64 + 255) / 256, 256>>>(p_pool);
    pool_kernel<<<(N_NODES + 255) / 256, 64>>>(p_h, p_pool);
    head_kernel<<<(NUM_GRAPHS * 32 + 255) / 256, 256>>>(p_pool, bng, bnb, bnm, bnv, fcw, fcb, out);
}

// round 4
// speedup vs baseline: 1.0041x; 1.0041x over previous
#include <cuda_runtime.h>
#include <cuda_bf16.h>
#include <math.h>

#define N_NODES   20000
#define N_EDGES   320000
#define E_TOT     (N_EDGES + N_NODES)   // 340000 with self loops
#define NUM_GRAPHS 64
#define MAXC      256

// ---------------- scratch (alloc-free: __device__ globals) ----------------
__device__ __align__(16) float g_h   [N_NODES * MAXC];
__device__ __align__(16) float g_xl  [N_NODES * MAXC];
__device__ __align__(16) float g_xr  [N_NODES * MAXC];
__device__ __align__(16) float g_ex  [E_TOT * 4];
__device__ __align__(16) float g_max [N_NODES * 4];
__device__ __align__(16) float g_den [N_NODES * 4];
__device__ __align__(16) float g_pool[NUM_GRAPHS * 64];
__device__ int g_src[E_TOT];
__device__ int g_dst[E_TOT];
__device__ int g_batch[N_NODES];
__device__ int g_is64;

// ---------------- helpers ----------------
__device__ __forceinline__ float lrelu(float v) { return v > 0.f ? v : 0.2f * v; }

__device__ __forceinline__ void atomicMaxF(float* addr, float value) {
    if (value >= 0.f) atomicMax((int*)addr, __float_as_int(value));
    else              atomicMin((unsigned int*)addr, __float_as_uint(value));
}

// -------- dtype detection: int64 indices have all-zero high words ----------
__global__ void detect_dtype(const int* __restrict__ ei32)
{
    int nonzero = 0;
    #pragma unroll 8
    for (int i = 0; i < 2048; i += 2) nonzero += (ei32[i + 1] != 0);
    g_is64 = (nonzero == 0) ? 1 : 0;
}

// -------- normalize edge_index + batch into int32, append self loops -------
__global__ void convert_indices(const void* __restrict__ ei_raw,
                                const void* __restrict__ batch_raw)
{
    int is64 = g_is64;
    int idx = blockIdx.x * blockDim.x + threadIdx.x;
    if (idx < N_EDGES) {
        if (is64) {
            const long long* e = (const long long*)ei_raw;
            g_src[idx] = (int)e[idx];
            g_dst[idx] = (int)e[N_EDGES + idx];
        } else {
            const int* e = (const int*)ei_raw;
            g_src[idx] = e[idx];
            g_dst[idx] = e[N_EDGES + idx];
        }
    } else if (idx < E_TOT) {
        g_src[idx] = idx - N_EDGES;
        g_dst[idx] = idx - N_EDGES;
    }
    if (idx < N_NODES) {
        g_batch[idx] = is64 ? (int)((const long long*)batch_raw)[idx]
                            : ((const int*)batch_raw)[idx];
    }
}

// ---------------- GEMM: C = A[N,K] @ W[K,M]; z picks (Wl->Xl)/(Wr->Xr) -----
__global__ void gemm_dual(const float* __restrict__ A,
                          const float* __restrict__ Wl, const float* __restrict__ Wr,
                          float* __restrict__ Xl, float* __restrict__ Xr,
                          int N, int K, int M)
{
    const float* B = blockIdx.z ? Wr : Wl;
    float*       C = blockIdx.z ? Xr : Xl;

    __shared__ float As[16][65];
    __shared__ float Bs[16][65];

    int tid = threadIdx.x;           // 256 threads
    int tx = tid & 15, ty = tid >> 4;
    int row0 = blockIdx.x * 64;
    int col0 = blockIdx.y * 64;

    float acc[4][4] = {};

    for (int k0 = 0; k0 < K; k0 += 16) {
        #pragma unroll
        for (int i = tid; i < 64 * 16; i += 256) {
            int r = i >> 4, kk = i & 15;
            int gr = row0 + r;
            As[kk][r] = (gr < N) ? A[(size_t)gr * K + k0 + kk] : 0.f;
        }
        #pragma unroll
        for (int i = tid; i < 16 * 64; i += 256) {
            int kk = i >> 6, c = i & 63;
            Bs[kk][c] = B[(size_t)(k0 + kk) * M + col0 + c];
        }
        __syncthreads();
        #pragma unroll
        for (int kk = 0; kk < 16; kk++) {
            float a[4], b[4];
            #pragma unroll
            for (int i = 0; i < 4; i++) a[i] = As[kk][ty * 4 + i];
            #pragma unroll
            for (int j = 0; j < 4; j++) b[j] = Bs[kk][tx * 4 + j];
            #pragma unroll
            for (int i = 0; i < 4; i++)
                #pragma unroll
                for (int j = 0; j < 4; j++)
                    acc[i][j] = fmaf(a[i], b[j], acc[i][j]);
        }
        __syncthreads();
    }
    #pragma unroll
    for (int i = 0; i < 4; i++) {
        int r = row0 + ty * 4 + i;
        if (r < N) {
            #pragma unroll
            for (int j = 0; j < 4; j++)
                C[(size_t)r * M + col0 + tx * 4 + j] = acc[i][j];
        }
    }
}

// -------- init per layer: agg = bias (broadcast), max = -inf, den = 0 ------
__global__ void init_layer(float* __restrict__ agg, float* __restrict__ nmax,
                           float* __restrict__ den, const float* __restrict__ bias,
                           int HC, int H)
{
    int idx = blockIdx.x * blockDim.x + threadIdx.x;
    int tot = N_NODES * HC;
    if (idx < tot) agg[idx] = bias[idx % HC];
    if (idx < N_NODES * H) { nmax[idx] = -INFINITY; den[idx] = 0.f; }
}

// -------- pass 1: per-edge per-head logits + segment max (warp/edge) -------
template<int H>
__global__ void edge_logits(const float* __restrict__ xl, const float* __restrict__ xr,
                            const float* __restrict__ att,
                            float* __restrict__ logits, float* __restrict__ nmax)
{
    int w = (blockIdx.x * blockDim.x + threadIdx.x) >> 5;
    int lane = threadIdx.x & 31;
    if (w >= E_TOT) return;
    int src = g_src[w], dst = g_dst[w];

    if (H == 4) {
        const float4* pl = (const float4*)(xl + (size_t)src * 256) + lane * 2;
        const float4* pr = (const float4*)(xr + (size_t)dst * 256) + lane * 2;
        const float4* pa = (const float4*)att + lane * 2;
        float s = 0.f;
        #pragma unroll
        for (int q = 0; q < 2; q++) {
            float4 a = pl[q], b = pr[q], t = pa[q];
            s += lrelu(a.x + b.x) * t.x + lrelu(a.y + b.y) * t.y
               + lrelu(a.z + b.z) * t.z + lrelu(a.w + b.w) * t.w;
        }
        s += __shfl_xor_sync(0xffffffffu, s, 1);
        s += __shfl_xor_sync(0xffffffffu, s, 2);
        s += __shfl_xor_sync(0xffffffffu, s, 4);
        if ((lane & 7) == 0) {
            int h = lane >> 3;
            logits[(size_t)w * 4 + h] = s;
            atomicMaxF(&nmax[dst * 4 + h], s);
        }
    } else {
        const float2* pl = (const float2*)(xl + (size_t)src * 64) + lane;
        const float2* pr = (const float2*)(xr + (size_t)dst * 64) + lane;
        const float2* pa = (const float2*)att + lane;
        float2 a = *pl, b = *pr, t = *pa;
        float s = lrelu(a.x + b.x) * t.x + lrelu(a.y + b.y) * t.y;
        #pragma unroll
        for (int o = 1; o < 32; o <<= 1) s += __shfl_xor_sync(0xffffffffu, s, o);
        if (lane == 0) {
            logits[w] = s;
            atomicMaxF(&nmax[dst], s);
        }
    }
}

// -------- pass 2: exp(logit - max), accumulate denominator -----------------
template<int H>
__global__ void edge_exp(float* __restrict__ logits,
                         const float* __restrict__ nmax, float* __restrict__ den)
{
    int idx = blockIdx.x * blockDim.x + threadIdx.x;
    if (idx >= E_TOT * H) return;
    int e = (H == 4) ? (idx >> 2) : idx;
    int h = (H == 4) ? (idx & 3) : 0;
    int dst = g_dst[e];
    float ex = expf(logits[idx] - nmax[dst * H + h]);
    logits[idx] = ex;
    atomicAdd(&den[dst * H + h], ex);
}

// -------- pass 3: agg[dst] += alpha * xl[src] (warp/edge, vector RED) ------
template<int H>
__global__ void edge_aggregate(const float* __restrict__ xl,
                               const float* __restrict__ ex, const float* __restrict__ den,
                               float* __restrict__ agg)
{
    int w = (blockIdx.x * blockDim.x + threadIdx.x) >> 5;
    int lane = threadIdx.x & 31;
    if (w >= E_TOT) return;
    int src = g_src[w], dst = g_dst[w];

    if (H == 4) {
        int h = lane >> 3;
        float alpha = ex[(size_t)w * 4 + h] / den[dst * 4 + h];
        const float4* pl = (const float4*)(xl + (size_t)src * 256) + lane * 2;
        float4*       pd = (float4*)(agg + (size_t)dst * 256) + lane * 2;
        #pragma unroll
        for (int q = 0; q < 2; q++) {
            float4 v = pl[q];
            atomicAdd(&pd[q], make_float4(alpha * v.x, alpha * v.y, alpha * v.z, alpha * v.w));
        }
    } else {
        float alpha = ex[w] / den[dst];
        const float2* pl = (const float2*)(xl + (size_t)src * 64) + lane;
        float2*       pd = (float2*)(agg + (size_t)dst * 64) + lane;
        float2 v = *pl;
        atomicAdd(pd, make_float2(alpha * v.x, alpha * v.y));
    }
}

// -------- pooling: batch is sorted -> run-length local accumulation --------
__global__ void pool_init(float* __restrict__ pooled)
{
    int idx = blockIdx.x * blockDim.x + threadIdx.x;
    if (idx < NUM_GRAPHS * 64) pooled[idx] = 0.f;
}

__global__ void pool_kernel(const float* __restrict__ h,
                            float* __restrict__ pooled)
{
    const int CHUNK = 256;
    int c = threadIdx.x;                  // 64 threads = channels
    int n0 = blockIdx.x * CHUNK;
    int n1 = min(n0 + CHUNK, N_NODES);
    if (n0 >= N_NODES) return;
    float acc = 0.f;
    int cur = g_batch[n0];
    for (int n = n0; n < n1; n++) {
        int g = g_batch[n];
        if (g != cur) {
            atomicAdd(&pooled[cur * 64 + c], acc);
            acc = 0.f; cur = g;
        }
        acc += h[(size_t)n * 64 + c];
    }
    atomicAdd(&pooled[cur * 64 + c], acc);
}

// -------- head: BN (eval) + FC ---------------------------------------------
__global__ void head_kernel(const float* __restrict__ pooled,
                            const float* __restrict__ gamma, const float* __restrict__ beta,
                            const float* __restrict__ mean,  const float* __restrict__ var,
                            const float* __restrict__ fcw,   const float* __restrict__ fcb,
                            float* __restrict__ out)
{
    int idx = blockIdx.x * blockDim.x + threadIdx.x;
    if (idx >= NUM_GRAPHS * 32) return;
    int g = idx >> 5, l = idx & 31;
    float s = 0.f;
    #pragma unroll 8
    for (int c = 0; c < 64; c++) {
        float xn = (pooled[g * 64 + c] - mean[c]) * rsqrtf(var[c] + 1e-5f) * gamma[c] + beta[c];
        s = fmaf(xn, fcw[c * 32 + l], s);
    }
    out[idx] = s + fcb[l];
}

// ---------------------------------------------------------------------------
static void run_layer(const float* hin, int K, int H,
                      const float* Wl, const float* Wr,
                      const float* att, const float* bias,
                      float* xl, float* xr, float* agg,
                      float* ex, float* nmax, float* den)
{
    int M = H * 64;
    dim3 ggrid((N_NODES + 63) / 64, M / 64, 2);
    gemm_dual<<<ggrid, 256>>>(hin, Wl, Wr, xl, xr, N_NODES, K, M);

    int tot = N_NODES * M;
    init_layer<<<(tot + 255) / 256, 256>>>(agg, nmax, den, bias, M, H);

    int warp_blocks = (E_TOT * 32 + 255) / 256;
    if (H == 4) {
        edge_logits<4><<<warp_blocks, 256>>>(xl, xr, att, ex, nmax);
        edge_exp<4><<<(E_TOT * 4 + 255) / 256, 256>>>(ex, nmax, den);
        edge_aggregate<4><<<warp_blocks, 256>>>(xl, ex, den, agg);
    } else {
        edge_logits<1><<<warp_blocks, 256>>>(xl, xr, att, ex, nmax);
        edge_exp<1><<<(E_TOT + 255) / 256, 256>>>(ex, nmax, den);
        edge_aggregate<1><<<warp_blocks, 256>>>(xl, ex, den, agg);
    }
}

extern "C" void kernel_launch(void* const* d_in, const int* in_sizes, int n_in,
                              void* d_out, int out_size)
{
    const float* x     = (const float*)d_in[0];
    const void*  ei    = d_in[1];
    const void*  batch = d_in[2];
    const float* Wl0 = (const float*)d_in[3];
    const float* Wr0 = (const float*)d_in[4];
    const float* att0= (const float*)d_in[5];
    const float* b0  = (const float*)d_in[6];
    const float* Wl1 = (const float*)d_in[7];
    const float* Wr1 = (const float*)d_in[8];
    const float* att1= (const float*)d_in[9];
    const float* b1  = (const float*)d_in[10];
    const float* Wl2 = (const float*)d_in[11];
    const float* Wr2 = (const float*)d_in[12];
    const float* att2= (const float*)d_in[13];
    const float* b2  = (const float*)d_in[14];
    const float* bng = (const float*)d_in[15];
    const float* bnb = (const float*)d_in[16];
    const float* bnm = (const float*)d_in[17];
    const float* bnv = (const float*)d_in[18];
    const float* fcw = (const float*)d_in[19];
    const float* fcb = (const float*)d_in[20];
    float* out = (float*)d_out;

    float *p_h, *p_xl, *p_xr, *p_ex, *p_max, *p_den, *p_pool;
    cudaGetSymbolAddress((void**)&p_h,    g_h);
    cudaGetSymbolAddress((void**)&p_xl,   g_xl);
    cudaGetSymbolAddress((void**)&p_xr,   g_xr);
    cudaGetSymbolAddress((void**)&p_ex,   g_ex);
    cudaGetSymbolAddress((void**)&p_max,  g_max);
    cudaGetSymbolAddress((void**)&p_den,  g_den);
    cudaGetSymbolAddress((void**)&p_pool, g_pool);

    // normalize index dtypes (int32 vs int64) into int32 scratch
    detect_dtype<<<1, 1>>>((const int*)ei);
    convert_indices<<<(E_TOT + 255) / 256, 256>>>(ei, batch);

    // layer 0: in=128, H=4  (x -> g_h[.,256])
    run_layer(x,   128, 4, Wl0, Wr0, att0, b0, p_xl, p_xr, p_h, p_ex, p_max, p_den);
    // layer 1: in=256, H=4  (g_h -> g_h)
    run_layer(p_h, 256, 4, Wl1, Wr1, att1, b1, p_xl, p_xr, p_h, p_ex, p_max, p_den);
    // layer 2: in=256, H=1  (g_h -> g_h[.,64])
    run_layer(p_h, 256, 1, Wl2, Wr2, att2, b2, p_xl, p_xr, p_h, p_ex, p_max, p_den);

    // global add pool + BN + FC
    pool_init<<<(NUM_GRAPHS * 64 + 255) / 256, 256>>>(p_pool);
    pool_kernel<<<(N_NODES + 255) / 256, 64>>>(p_h, p_pool);
    head_kernel<<<(NUM_GRAPHS * 32 + 255) / 256, 256>>>(p_pool, bng, bnb, bnm, bnv, fcw, fcb, out);
}

// round 5
// speedup vs baseline: 1.0058x; 1.0017x over previous
#include <cuda_runtime.h>
#include <cuda_bf16.h>
#include <math.h>

#define N_NODES   20000
#define N_EDGES   320000
#define E_TOT     (N_EDGES + N_NODES)   // 340000 with self loops
#define NUM_GRAPHS 64
#define MAXC      256

// ---------------- scratch (alloc-free: __device__ globals) ----------------
__device__ __align__(16) float g_h   [N_NODES * MAXC];
__device__ __align__(16) float g_xl  [N_NODES * MAXC];
__device__ __align__(16) float g_xr  [N_NODES * MAXC];
__device__ __align__(16) float g_ex  [E_TOT * 4];
__device__ __align__(16) float g_max [N_NODES * 4];
__device__ __align__(16) float g_den [N_NODES * 4];
__device__ __align__(16) float g_pool[NUM_GRAPHS * 64];
__device__ int g_src[E_TOT];
__device__ int g_dst[E_TOT];
__device__ int g_batch[N_NODES];
__device__ int g_is64;

// ---------------- helpers ----------------
__device__ __forceinline__ float lrelu(float v) { return v > 0.f ? v : 0.2f * v; }

__device__ __forceinline__ void atomicMaxF(float* addr, float value) {
    if (value >= 0.f) atomicMax((int*)addr, __float_as_int(value));
    else              atomicMin((unsigned int*)addr, __float_as_uint(value));
}

// -------- dtype detection: int64 indices have all-zero high words ----------
__global__ void detect_dtype(const int* __restrict__ ei32)
{
    int nonzero = 0;
    #pragma unroll 8
    for (int i = 0; i < 2048; i += 2) nonzero += (ei32[i + 1] != 0);
    g_is64 = (nonzero == 0) ? 1 : 0;
}

// -------- normalize edge_index + batch into int32, append self loops -------
__global__ void convert_indices(const void* __restrict__ ei_raw,
                                const void* __restrict__ batch_raw)
{
    int is64 = g_is64;
    int idx = blockIdx.x * blockDim.x + threadIdx.x;
    if (idx < N_EDGES) {
        if (is64) {
            const long long* e = (const long long*)ei_raw;
            g_src[idx] = (int)e[idx];
            g_dst[idx] = (int)e[N_EDGES + idx];
        } else {
            const int* e = (const int*)ei_raw;
            g_src[idx] = e[idx];
            g_dst[idx] = e[N_EDGES + idx];
        }
    } else if (idx < E_TOT) {
        g_src[idx] = idx - N_EDGES;
        g_dst[idx] = idx - N_EDGES;
    }
    if (idx < N_NODES) {
        g_batch[idx] = is64 ? (int)((const long long*)batch_raw)[idx]
                            : ((const int*)batch_raw)[idx];
    }
}

// ---------------- GEMM: C = A[N,K] @ W[K,M]; z picks (Wl->Xl)/(Wr->Xr) -----
__global__ void gemm_dual(const float* __restrict__ A,
                          const float* __restrict__ Wl, const float* __restrict__ Wr,
                          float* __restrict__ Xl, float* __restrict__ Xr,
                          int N, int K, int M)
{
    const float* B = blockIdx.z ? Wr : Wl;
    float*       C = blockIdx.z ? Xr : Xl;

    __shared__ float As[16][65];
    __shared__ float Bs[16][65];

    int tid = threadIdx.x;           // 256 threads
    int tx = tid & 15, ty = tid >> 4;
    int row0 = blockIdx.x * 64;
    int col0 = blockIdx.y * 64;

    float acc[4][4] = {};

    for (int k0 = 0; k0 < K; k0 += 16) {
        #pragma unroll
        for (int i = tid; i < 64 * 16; i += 256) {
            int r = i >> 4, kk = i & 15;
            int gr = row0 + r;
            As[kk][r] = (gr < N) ? A[(size_t)gr * K + k0 + kk] : 0.f;
        }
        #pragma unroll
        for (int i = tid; i < 16 * 64; i += 256) {
            int kk = i >> 6, c = i & 63;
            Bs[kk][c] = B[(size_t)(k0 + kk) * M + col0 + c];
        }
        __syncthreads();
        #pragma unroll
        for (int kk = 0; kk < 16; kk++) {
            float a[4], b[4];
            #pragma unroll
            for (int i = 0; i < 4; i++) a[i] = As[kk][ty * 4 + i];
            #pragma unroll
            for (int j = 0; j < 4; j++) b[j] = Bs[kk][tx * 4 + j];
            #pragma unroll
            for (int i = 0; i < 4; i++)
                #pragma unroll
                for (int j = 0; j < 4; j++)
                    acc[i][j] = fmaf(a[i], b[j], acc[i][j]);
        }
        __syncthreads();
    }
    #pragma unroll
    for (int i = 0; i < 4; i++) {
        int r = row0 + ty * 4 + i;
        if (r < N) {
            #pragma unroll
            for (int j = 0; j < 4; j++)
                C[(size_t)r * M + col0 + tx * 4 + j] = acc[i][j];
        }
    }
}

// -------- init per layer: agg = bias (broadcast), max = -inf, den = 0 ------
__global__ void init_layer(float* __restrict__ agg, float* __restrict__ nmax,
                           float* __restrict__ den, const float* __restrict__ bias,
                           int HC, int H)
{
    int idx = blockIdx.x * blockDim.x + threadIdx.x;
    int tot = N_NODES * HC;
    if (idx < tot) agg[idx] = bias[idx % HC];
    if (idx < N_NODES * H) { nmax[idx] = -INFINITY; den[idx] = 0.f; }
}

// -------- pass 1: per-edge per-head logits + segment max (warp/edge) -------
template<int H>
__global__ void edge_logits(const float* __restrict__ xl, const float* __restrict__ xr,
                            const float* __restrict__ att,
                            float* __restrict__ logits, float* __restrict__ nmax)
{
    int w = (blockIdx.x * blockDim.x + threadIdx.x) >> 5;
    int lane = threadIdx.x & 31;
    if (w >= E_TOT) return;
    int src = g_src[w], dst = g_dst[w];

    if (H == 4) {
        const float4* pl = (const float4*)(xl + (size_t)src * 256) + lane * 2;
        const float4* pr = (const float4*)(xr + (size_t)dst * 256) + lane * 2;
        const float4* pa = (const float4*)att + lane * 2;
        float s = 0.f;
        #pragma unroll
        for (int q = 0; q < 2; q++) {
            float4 a = pl[q], b = pr[q], t = pa[q];
            s += lrelu(a.x + b.x) * t.x + lrelu(a.y + b.y) * t.y
               + lrelu(a.z + b.z) * t.z + lrelu(a.w + b.w) * t.w;
        }
        s += __shfl_xor_sync(0xffffffffu, s, 1);
        s += __shfl_xor_sync(0xffffffffu, s, 2);
        s += __shfl_xor_sync(0xffffffffu, s, 4);
        if ((lane & 7) == 0) {
            int h = lane >> 3;
            logits[(size_t)w * 4 + h] = s;
            atomicMaxF(&nmax[dst * 4 + h], s);
        }
    } else {
        const float2* pl = (const float2*)(xl + (size_t)src * 64) + lane;
        const float2* pr = (const float2*)(xr + (size_t)dst * 64) + lane;
        const float2* pa = (const float2*)att + lane;
        float2 a = *pl, b = *pr, t = *pa;
        float s = lrelu(a.x + b.x) * t.x + lrelu(a.y + b.y) * t.y;
        #pragma unroll
        for (int o = 1; o < 32; o <<= 1) s += __shfl_xor_sync(0xffffffffu, s, o);
        if (lane == 0) {
            logits[w] = s;
            atomicMaxF(&nmax[dst], s);
        }
    }
}

// -------- pass 2: exp(logit - max), accumulate denominator -----------------
template<int H>
__global__ void edge_exp(float* __restrict__ logits,
                         const float* __restrict__ nmax, float* __restrict__ den)
{
    int idx = blockIdx.x * blockDim.x + threadIdx.x;
    if (idx >= E_TOT * H) return;
    int e = (H == 4) ? (idx >> 2) : idx;
    int h = (H == 4) ? (idx & 3) : 0;
    int dst = g_dst[e];
    float ex = expf(logits[idx] - nmax[dst * H + h]);
    logits[idx] = ex;
    atomicAdd(&den[dst * H + h], ex);
}

// -------- pass 3: agg[dst] += alpha * xl[src] (warp/edge, vector RED) ------
template<int H>
__global__ void edge_aggregate(const float* __restrict__ xl,
                               const float* __restrict__ ex, const float* __restrict__ den,
                               float* __restrict__ agg)
{
    int w = (blockIdx.x * blockDim.x + threadIdx.x) >> 5;
    int lane = threadIdx.x & 31;
    if (w >= E_TOT) return;
    int src = g_src[w], dst = g_dst[w];

    if (H == 4) {
        int h = lane >> 3;
        float alpha = ex[(size_t)w * 4 + h] / den[dst * 4 + h];
        const float4* pl = (const float4*)(xl + (size_t)src * 256) + lane * 2;
        float4*       pd = (float4*)(agg + (size_t)dst * 256) + lane * 2;
        #pragma unroll
        for (int q = 0; q < 2; q++) {
            float4 v = pl[q];
            atomicAdd(&pd[q], make_float4(alpha * v.x, alpha * v.y, alpha * v.z, alpha * v.w));
        }
    } else {
        float alpha = ex[w] / den[dst];
        const float2* pl = (const float2*)(xl + (size_t)src * 64) + lane;
        float2*       pd = (float2*)(agg + (size_t)dst * 64) + lane;
        float2 v = *pl;
        atomicAdd(pd, make_float2(alpha * v.x, alpha * v.y));
    }
}

// -------- pooling: batch is sorted -> run-length local accumulation --------
__global__ void pool_init(float* __restrict__ pooled)
{
    int idx = blockIdx.x * blockDim.x + threadIdx.x;
    if (idx < NUM_GRAPHS * 64) pooled[idx] = 0.f;
}

__global__ void pool_kernel(const float* __restrict__ h,
                            float* __restrict__ pooled)
{
    const int CHUNK = 256;
    int c = threadIdx.x;                  // 64 threads = channels
    int n0 = blockIdx.x * CHUNK;
    int n1 = min(n0 + CHUNK, N_NODES);
    if (n0 >= N_NODES) return;
    float acc = 0.f;
    int cur = g_batch[n0];
    for (int n = n0; n < n1; n++) {
        int g = g_batch[n];
        if (g != cur) {
            atomicAdd(&pooled[cur * 64 + c], acc);
            acc = 0.f; cur = g;
        }
        acc += h[(size_t)n * 64 + c];
    }
    atomicAdd(&pooled[cur * 64 + c], acc);
}

// -------- head: BN (eval) + FC ---------------------------------------------
__global__ void head_kernel(const float* __restrict__ pooled,
                            const float* __restrict__ gamma, const float* __restrict__ beta,
                            const float* __restrict__ mean,  const float* __restrict__ var,
                            const float* __restrict__ fcw,   const float* __restrict__ fcb,
                            float* __restrict__ out)
{
    int idx = blockIdx.x * blockDim.x + threadIdx.x;
    if (idx >= NUM_GRAPHS * 32) return;
    int g = idx >> 5, l = idx & 31;
    float s = 0.f;
    #pragma unroll 8
    for (int c = 0; c < 64; c++) {
        float xn = (pooled[g * 64 + c] - mean[c]) * rsqrtf(var[c] + 1e-5f) * gamma[c] + beta[c];
        s = fmaf(xn, fcw[c * 32 + l], s);
    }
    out[idx] = s + fcb[l];
}

// ---------------------------------------------------------------------------
static void run_layer(const float* hin, int K, int H,
                      const float* Wl, const float* Wr,
                      const float* att, const float* bias,
                      float* xl, float* xr, float* agg,
                      float* ex, float* nmax, float* den)
{
    int M = H * 64;
    dim3 ggrid((N_NODES + 63) / 64, M / 64, 2);
    gemm_dual<<<ggrid, 256>>>(hin, Wl, Wr, xl, xr, N_NODES, K, M);

    int tot = N_NODES * M;
    init_layer<<<(tot + 255) / 256, 256>>>(agg, nmax, den, bias, M, H);

    int warp_blocks = (E_TOT * 32 + 255) / 256;
    if (H == 4) {
        edge_logits<4><<<warp_blocks, 256>>>(xl, xr, att, ex, nmax);
        edge_exp<4><<<(E_TOT * 4 + 255) / 256, 256>>>(ex, nmax, den);
        edge_aggregate<4><<<warp_blocks, 256>>>(xl, ex, den, agg);
    } else {
        edge_logits<1><<<warp_blocks, 256>>>(xl, xr, att, ex, nmax);
        edge_exp<1><<<(E_TOT + 255) / 256, 256>>>(ex, nmax, den);
        edge_aggregate<1><<<warp_blocks, 256>>>(xl, ex, den, agg);
    }
}

extern "C" void kernel_launch(void* const* d_in, const int* in_sizes, int n_in,
                              void* d_out, int out_size)
{
    const float* x     = (const float*)d_in[0];
    const void*  ei    = d_in[1];
    const void*  batch = d_in[2];
    const float* Wl0 = (const float*)d_in[3];
    const float* Wr0 = (const float*)d_in[4];
    const float* att0= (const float*)d_in[5];
    const float* b0  = (const float*)d_in[6];
    const float* Wl1 = (const float*)d_in[7];
    const float* Wr1 = (const float*)d_in[8];
    const float* att1= (const float*)d_in[9];
    const float* b1  = (const float*)d_in[10];
    const float* Wl2 = (const float*)d_in[11];
    const float* Wr2 = (const float*)d_in[12];
    const float* att2= (const float*)d_in[13];
    const float* b2  = (const float*)d_in[14];
    const float* bng = (const float*)d_in[15];
    const float* bnb = (const float*)d_in[16];
    const float* bnm = (const float*)d_in[17];
    const float* bnv = (const float*)d_in[18];
    const float* fcw = (const float*)d_in[19];
    const float* fcb = (const float*)d_in[20];
    float* out = (float*)d_out;

    float *p_h, *p_xl, *p_xr, *p_ex, *p_max, *p_den, *p_pool;
    cudaGetSymbolAddress((void**)&p_h,    g_h);
    cudaGetSymbolAddress((void**)&p_xl,   g_xl);
    cudaGetSymbolAddress((void**)&p_xr,   g_xr);
    cudaGetSymbolAddress((void**)&p_ex,   g_ex);
    cudaGetSymbolAddress((void**)&p_max,  g_max);
    cudaGetSymbolAddress((void**)&p_den,  g_den);
    cudaGetSymbolAddress((void**)&p_pool, g_pool);

    // normalize index dtypes (int32 vs int64) into int32 scratch
    detect_dtype<<<1, 1>>>((const int*)ei);
    convert_indices<<<(E_TOT + 255) / 256, 256>>>(ei, batch);

    // layer 0: in=128, H=4  (x -> g_h[.,256])
    run_layer(x,   128, 4, Wl0, Wr0, att0, b0, p_xl, p_xr, p_h, p_ex, p_max, p_den);
    // layer 1: in=256, H=4  (g_h -> g_h)
    run_layer(p_h, 256, 4, Wl1, Wr1, att1, b1, p_xl, p_xr, p_h, p_ex, p_max, p_den);
    // layer 2: in=256, H=1  (g_h -> g_h[.,64])
    run_layer(p_h, 256, 1, Wl2, Wr2, att2, b2, p_xl, p_xr, p_h, p_ex, p_max, p_den);

    // global add pool + BN + FC
    pool_init<<<(NUM_GRAPHS * 64 + 255) / 256, 256>>>(p_pool);
    pool_kernel<<<(N_NODES + 255) / 256, 64>>>(p_h, p_pool);
    head_kernel<<<(NUM_GRAPHS * 32 + 255) / 256, 256>>>(p_pool, bng, bnb, bnm, bnv, fcw, fcb, out);
}

// round 6
// speedup vs baseline: 1.0063x; 1.0005x over previous
#include <cuda_runtime.h>
#include <cuda_bf16.h>
#include <math.h>

#define N_NODES   20000
#define N_EDGES   320000
#define E_TOT     (N_EDGES + N_NODES)   // 340000 with self loops
#define NUM_GRAPHS 64
#define MAXC      256

// ---------------- scratch (alloc-free: __device__ globals) ----------------
__device__ __align__(16) float g_h   [N_NODES * MAXC];
__device__ __align__(16) float g_xl  [N_NODES * MAXC];
__device__ __align__(16) float g_xr  [N_NODES * MAXC];
__device__ __align__(16) float g_ex  [E_TOT * 4];
__device__ __align__(16) float g_max [N_NODES * 4];
__device__ __align__(16) float g_den [N_NODES * 4];
__device__ __align__(16) float g_pool[NUM_GRAPHS * 64];
__device__ int g_src[E_TOT];
__device__ int g_dst[E_TOT];
__device__ int g_batch[N_NODES];
__device__ int g_is64;

// ---------------- helpers ----------------
__device__ __forceinline__ float lrelu(float v) { return v > 0.f ? v : 0.2f * v; }

__device__ __forceinline__ void atomicMaxF(float* addr, float value) {
    if (value >= 0.f) atomicMax((int*)addr, __float_as_int(value));
    else              atomicMin((unsigned int*)addr, __float_as_uint(value));
}

// -------- dtype detection: int64 indices have all-zero high words ----------
__global__ void detect_dtype(const int* __restrict__ ei32)
{
    int nonzero = 0;
    #pragma unroll 8
    for (int i = 0; i < 2048; i += 2) nonzero += (ei32[i + 1] != 0);
    g_is64 = (nonzero == 0) ? 1 : 0;
}

// -------- normalize edge_index + batch into int32, append self loops -------
__global__ void convert_indices(const void* __restrict__ ei_raw,
                                const void* __restrict__ batch_raw)
{
    int is64 = g_is64;
    int idx = blockIdx.x * blockDim.x + threadIdx.x;
    if (idx < N_EDGES) {
        if (is64) {
            const long long* e = (const long long*)ei_raw;
            g_src[idx] = (int)e[idx];
            g_dst[idx] = (int)e[N_EDGES + idx];
        } else {
            const int* e = (const int*)ei_raw;
            g_src[idx] = e[idx];
            g_dst[idx] = e[N_EDGES + idx];
        }
    } else if (idx < E_TOT) {
        g_src[idx] = idx - N_EDGES;
        g_dst[idx] = idx - N_EDGES;
    }
    if (idx < N_NODES) {
        g_batch[idx] = is64 ? (int)((const long long*)batch_raw)[idx]
                            : ((const int*)batch_raw)[idx];
    }
}

// ---------------- GEMM: C = A[N,K] @ W[K,M]; z picks (Wl->Xl)/(Wr->Xr) -----
__global__ void gemm_dual(const float* __restrict__ A,
                          const float* __restrict__ Wl, const float* __restrict__ Wr,
                          float* __restrict__ Xl, float* __restrict__ Xr,
                          int N, int K, int M)
{
    const float* B = blockIdx.z ? Wr : Wl;
    float*       C = blockIdx.z ? Xr : Xl;

    __shared__ float As[16][65];
    __shared__ float Bs[16][65];

    int tid = threadIdx.x;           // 256 threads
    int tx = tid & 15, ty = tid >> 4;
    int row0 = blockIdx.x * 64;
    int col0 = blockIdx.y * 64;

    float acc[4][4] = {};

    for (int k0 = 0; k0 < K; k0 += 16) {
        #pragma unroll
        for (int i = tid; i < 64 * 16; i += 256) {
            int r = i >> 4, kk = i & 15;
            int gr = row0 + r;
            As[kk][r] = (gr < N) ? A[(size_t)gr * K + k0 + kk] : 0.f;
        }
        #pragma unroll
        for (int i = tid; i < 16 * 64; i += 256) {
            int kk = i >> 6, c = i & 63;
            Bs[kk][c] = B[(size_t)(k0 + kk) * M + col0 + c];
        }
        __syncthreads();
        #pragma unroll
        for (int kk = 0; kk < 16; kk++) {
            float a[4], b[4];
            #pragma unroll
            for (int i = 0; i < 4; i++) a[i] = As[kk][ty * 4 + i];
            #pragma unroll
            for (int j = 0; j < 4; j++) b[j] = Bs[kk][tx * 4 + j];
            #pragma unroll
            for (int i = 0; i < 4; i++)
                #pragma unroll
                for (int j = 0; j < 4; j++)
                    acc[i][j] = fmaf(a[i], b[j], acc[i][j]);
        }
        __syncthreads();
    }
    #pragma unroll
    for (int i = 0; i < 4; i++) {
        int r = row0 + ty * 4 + i;
        if (r < N) {
            #pragma unroll
            for (int j = 0; j < 4; j++)
                C[(size_t)r * M + col0 + tx * 4 + j] = acc[i][j];
        }
    }
}

// -------- init per layer: agg = bias (broadcast), max = -inf, den = 0 ------
__global__ void init_layer(float* __restrict__ agg, float* __restrict__ nmax,
                           float* __restrict__ den, const float* __restrict__ bias,
                           int HC, int H)
{
    int idx = blockIdx.x * blockDim.x + threadIdx.x;
    int tot = N_NODES * HC;
    if (idx < tot) agg[idx] = bias[idx % HC];
    if (idx < N_NODES * H) { nmax[idx] = -INFINITY; den[idx] = 0.f; }
}

// -------- pass 1: per-edge per-head logits + segment max (warp/edge) -------
template<int H>
__global__ void edge_logits(const float* __restrict__ xl, const float* __restrict__ xr,
                            const float* __restrict__ att,
                            float* __restrict__ logits, float* __restrict__ nmax)
{
    int w = (blockIdx.x * blockDim.x + threadIdx.x) >> 5;
    int lane = threadIdx.x & 31;
    if (w >= E_TOT) return;
    int src = g_src[w], dst = g_dst[w];

    if (H == 4) {
        const float4* pl = (const float4*)(xl + (size_t)src * 256) + lane * 2;
        const float4* pr = (const float4*)(xr + (size_t)dst * 256) + lane * 2;
        const float4* pa = (const float4*)att + lane * 2;
        float s = 0.f;
        #pragma unroll
        for (int q = 0; q < 2; q++) {
            float4 a = pl[q], b = pr[q], t = pa[q];
            s += lrelu(a.x + b.x) * t.x + lrelu(a.y + b.y) * t.y
               + lrelu(a.z + b.z) * t.z + lrelu(a.w + b.w) * t.w;
        }
        s += __shfl_xor_sync(0xffffffffu, s, 1);
        s += __shfl_xor_sync(0xffffffffu, s, 2);
        s += __shfl_xor_sync(0xffffffffu, s, 4);
        if ((lane & 7) == 0) {
            int h = lane >> 3;
            logits[(size_t)w * 4 + h] = s;
            atomicMaxF(&nmax[dst * 4 + h], s);
        }
    } else {
        const float2* pl = (const float2*)(xl + (size_t)src * 64) + lane;
        const float2* pr = (const float2*)(xr + (size_t)dst * 64) + lane;
        const float2* pa = (const float2*)att + lane;
        float2 a = *pl, b = *pr, t = *pa;
        float s = lrelu(a.x + b.x) * t.x + lrelu(a.y + b.y) * t.y;
        #pragma unroll
        for (int o = 1; o < 32; o <<= 1) s += __shfl_xor_sync(0xffffffffu, s, o);
        if (lane == 0) {
            logits[w] = s;
            atomicMaxF(&nmax[dst], s);
        }
    }
}

// -------- pass 2: exp(logit - max), accumulate denominator -----------------
template<int H>
__global__ void edge_exp(float* __restrict__ logits,
                         const float* __restrict__ nmax, float* __restrict__ den)
{
    int idx = blockIdx.x * blockDim.x + threadIdx.x;
    if (idx >= E_TOT * H) return;
    int e = (H == 4) ? (idx >> 2) : idx;
    int h = (H == 4) ? (idx & 3) : 0;
    int dst = g_dst[e];
    float ex = expf(logits[idx] - nmax[dst * H + h]);
    logits[idx] = ex;
    atomicAdd(&den[dst * H + h], ex);
}

// -------- pass 3: agg[dst] += alpha * xl[src] (warp/edge, vector RED) ------
template<int H>
__global__ void edge_aggregate(const float* __restrict__ xl,
                               const float* __restrict__ ex, const float* __restrict__ den,
                               float* __restrict__ agg)
{
    int w = (blockIdx.x * blockDim.x + threadIdx.x) >> 5;
    int lane = threadIdx.x & 31;
    if (w >= E_TOT) return;
    int src = g_src[w], dst = g_dst[w];

    if (H == 4) {
        int h = lane >> 3;
        float alpha = ex[(size_t)w * 4 + h] / den[dst * 4 + h];
        const float4* pl = (const float4*)(xl + (size_t)src * 256) + lane * 2;
        float4*       pd = (float4*)(agg + (size_t)dst * 256) + lane * 2;
        #pragma unroll
        for (int q = 0; q < 2; q++) {
            float4 v = pl[q];
            atomicAdd(&pd[q], make_float4(alpha * v.x, alpha * v.y, alpha * v.z, alpha * v.w));
        }
    } else {
        float alpha = ex[w] / den[dst];
        const float2* pl = (const float2*)(xl + (size_t)src * 64) + lane;
        float2*       pd = (float2*)(agg + (size_t)dst * 64) + lane;
        float2 v = *pl;
        atomicAdd(pd, make_float2(alpha * v.x, alpha * v.y));
    }
}

// -------- pooling: batch is sorted -> run-length local accumulation --------
__global__ void pool_init(float* __restrict__ pooled)
{
    int idx = blockIdx.x * blockDim.x + threadIdx.x;
    if (idx < NUM_GRAPHS * 64) pooled[idx] = 0.f;
}

__global__ void pool_kernel(const float* __restrict__ h,
                            float* __restrict__ pooled)
{
    const int CHUNK = 256;
    int c = threadIdx.x;                  // 64 threads = channels
    int n0 = blockIdx.x * CHUNK;
    int n1 = min(n0 + CHUNK, N_NODES);
    if (n0 >= N_NODES) return;
    float acc = 0.f;
    int cur = g_batch[n0];
    for (int n = n0; n < n1; n++) {
        int g = g_batch[n];
        if (g != cur) {
            atomicAdd(&pooled[cur * 64 + c], acc);
            acc = 0.f; cur = g;
        }
        acc += h[(size_t)n * 64 + c];
    }
    atomicAdd(&pooled[cur * 64 + c], acc);
}

// -------- head: BN (eval) + FC ---------------------------------------------
__global__ void head_kernel(const float* __restrict__ pooled,
                            const float* __restrict__ gamma, const float* __restrict__ beta,
                            const float* __restrict__ mean,  const float* __restrict__ var,
                            const float* __restrict__ fcw,   const float* __restrict__ fcb,
                            float* __restrict__ out)
{
    int idx = blockIdx.x * blockDim.x + threadIdx.x;
    if (idx >= NUM_GRAPHS * 32) return;
    int g = idx >> 5, l = idx & 31;
    float s = 0.f;
    #pragma unroll 8
    for (int c = 0; c < 64; c++) {
        float xn = (pooled[g * 64 + c] - mean[c]) * rsqrtf(var[c] + 1e-5f) * gamma[c] + beta[c];
        s = fmaf(xn, fcw[c * 32 + l], s);
    }
    out[idx] = s + fcb[l];
}

// ---------------------------------------------------------------------------
static void run_layer(const float* hin, int K, int H,
                      const float* Wl, const float* Wr,
                      const float* att, const float* bias,
                      float* xl, float* xr, float* agg,
                      float* ex, float* nmax, float* den)
{
    int M = H * 64;
    dim3 ggrid((N_NODES + 63) / 64, M / 64, 2);
    gemm_dual<<<ggrid, 256>>>(hin, Wl, Wr, xl, xr, N_NODES, K, M);

    int tot = N_NODES * M;
    init_layer<<<(tot + 255) / 256, 256>>>(agg, nmax, den, bias, M, H);

    int warp_blocks = (E_TOT * 32 + 255) / 256;
    if (H == 4) {
        edge_logits<4><<<warp_blocks, 256>>>(xl, xr, att, ex, nmax);
        edge_exp<4><<<(E_TOT * 4 + 255) / 256, 256>>>(ex, nmax, den);
        edge_aggregate<4><<<warp_blocks, 256>>>(xl, ex, den, agg);
    } else {
        edge_logits<1><<<warp_blocks, 256>>>(xl, xr, att, ex, nmax);
        edge_exp<1><<<(E_TOT + 255) / 256, 256>>>(ex, nmax, den);
        edge_aggregate<1><<<warp_blocks, 256>>>(xl, ex, den, agg);
    }
}

extern "C" void kernel_launch(void* const* d_in, const int* in_sizes, int n_in,
                              void* d_out, int out_size)
{
    const float* x     = (const float*)d_in[0];
    const void*  ei    = d_in[1];
    const void*  batch = d_in[2];
    const float* Wl0 = (const float*)d_in[3];
    const float* Wr0 = (const float*)d_in[4];
    const float* att0= (const float*)d_in[5];
    const float* b0  = (const float*)d_in[6];
    const float* Wl1 = (const float*)d_in[7];
    const float* Wr1 = (const float*)d_in[8];
    const float* att1= (const float*)d_in[9];
    const float* b1  = (const float*)d_in[10];
    const float* Wl2 = (const float*)d_in[11];
    const float* Wr2 = (const float*)d_in[12];
    const float* att2= (const float*)d_in[13];
    const float* b2  = (const float*)d_in[14];
    const float* bng = (const float*)d_in[15];
    const float* bnb = (const float*)d_in[16];
    const float* bnm = (const float*)d_in[17];
    const float* bnv = (const float*)d_in[18];
    const float* fcw = (const float*)d_in[19];
    const float* fcb = (const float*)d_in[20];
    float* out = (float*)d_out;

    float *p_h, *p_xl, *p_xr, *p_ex, *p_max, *p_den, *p_pool;
    cudaGetSymbolAddress((void**)&p_h,    g_h);
    cudaGetSymbolAddress((void**)&p_xl,   g_xl);
    cudaGetSymbolAddress((void**)&p_xr,   g_xr);
    cudaGetSymbolAddress((void**)&p_ex,   g_ex);
    cudaGetSymbolAddress((void**)&p_max,  g_max);
    cudaGetSymbolAddress((void**)&p_den,  g_den);
    cudaGetSymbolAddress((void**)&p_pool, g_pool);

    // normalize index dtypes (int32 vs int64) into int32 scratch
    detect_dtype<<<1, 1>>>((const int*)ei);
    convert_indices<<<(E_TOT + 255) / 256, 256>>>(ei, batch);

    // layer 0: in=128, H=4  (x -> g_h[.,256])
    run_layer(x,   128, 4, Wl0, Wr0, att0, b0, p_xl, p_xr, p_h, p_ex, p_max, p_den);
    // layer 1: in=256, H=4  (g_h -> g_h)
    run_layer(p_h, 256, 4, Wl1, Wr1, att1, b1, p_xl, p_xr, p_h, p_ex, p_max, p_den);
    // layer 2: in=256, H=1  (g_h -> g_h[.,64])
    run_layer(p_h, 256, 1, Wl2, Wr2, att2, b2, p_xl, p_xr, p_h, p_ex, p_max, p_den);

    // global add pool + BN + FC
    pool_init<<<(NUM_GRAPHS * 64 + 255) / 256, 256>>>(p_pool);
    pool_kernel<<<(N_NODES + 255) / 256, 64>>>(p_h, p_pool);
    head_kernel<<<(NUM_GRAPHS * 32 + 255) / 256, 256>>>(p_pool, bng, bnb, bnm, bnv, fcw, fcb, out);
}